// round 9
// baseline (speedup 1.0000x reference)
#include <cuda_runtime.h>
#include <cuda_bf16.h>
#include <cstdint>

// ---------------------------------------------------------------------------
// IterativeEmbeddingModel: 2 iterations of
//   emb <- concat(emb@T1, seg_sum(emb[col],row)@T2, seg_sum_anti(...)@T3)
// R9 (vs R8: gemm 60.8us, tensor 33.4%, occ 24.7%, 1 CTA/SM @150KB smem):
//  - BM=64 tile + B in FRAGMENT-ORDER smem (one uint4 = {b0h,b1h,b0l,b1l}
//    per lane per tile per kstep, written by convert_theta): smem 150KB ->
//    100,352B => 2 CTAs/SM; B hi+lo fetched by ONE LDS.128.
//  - __launch_bounds__(512,2) caps regs at 64 so both CTAs fit the regfile.
//  - Warp = m16 x n16 (16 warps = 4 m-groups x 4 n-groups).
//  Same split-bf16 3-term math (rel_err ~6e-6, tolerance 1e-3).
// ---------------------------------------------------------------------------

#define NMAX 50000
#define EMAX 400000
#define DIM  192
#define PP   64

// Scratch (device globals; no allocation APIs allowed)
__device__ int      g_count[2 * NMAX];
__device__ int      g_cursor[2 * NMAX];
__device__ int      g_rowstart[2 * (NMAX + 1)];
__device__ int      g_blocksum[2 * 128];
__device__ int      g_cols[2 * EMAX];
__device__ float    g_emb1[(size_t)NMAX * DIM];   // iteration-1 output
__device__ float    g_Y[(size_t)NMAX * 128];      // [Y2 | Y3] per row
__device__ uint4    g_Bfrag[3 * 12 * 8 * 32];     // thetas, fragment-order

__device__ __forceinline__ uint32_t smem_to_u32(const void* p) {
    uint32_t a;
    asm("{ .reg .u64 t; cvta.to.shared.u64 t, %1; cvt.u32.u64 %0, t; }"
        : "=r"(a) : "l"(p));
    return a;
}

// ---- CSR build ------------------------------------------------------------
__global__ void zero_counts_kernel() {
    int i = blockIdx.x * blockDim.x + threadIdx.x;
    if (i < 2 * NMAX) g_count[i] = 0;
}

__global__ void hist_kernel(const int* __restrict__ e0, const int* __restrict__ e1, int nE) {
    int i = blockIdx.x * blockDim.x + threadIdx.x;
    if (i >= 2 * nE) return;
    int l = (i < nE) ? 0 : 1;
    const int* p = l ? e1 : e0;
    int e = l ? (i - nE) : i;
    int d = p[e];
    atomicAdd(&g_count[l * NMAX + d], 1);
}

__global__ void scan_partial_kernel(int n) {
    __shared__ int warp_sums[16];
    int l = blockIdx.y;
    int i = blockIdx.x * 512 + threadIdx.x;
    int lane = threadIdx.x & 31;
    int w = threadIdx.x >> 5;
    int v = (i < n) ? g_count[l * NMAX + i] : 0;
    int s = v;
#pragma unroll
    for (int o = 1; o < 32; o <<= 1) {
        int t = __shfl_up_sync(0xFFFFFFFFu, s, o);
        if (lane >= o) s += t;
    }
    if (lane == 31) warp_sums[w] = s;
    __syncthreads();
    if (w == 0) {
        int ws = (lane < 16) ? warp_sums[lane] : 0;
#pragma unroll
        for (int o = 1; o < 16; o <<= 1) {
            int t = __shfl_up_sync(0xFFFFFFFFu, ws, o);
            if (lane >= o) ws += t;
        }
        if (lane < 16) warp_sums[lane] = ws;
    }
    __syncthreads();
    int base = (w > 0) ? warp_sums[w - 1] : 0;
    if (i < n) g_rowstart[l * (NMAX + 1) + i] = base + s - v;
    if (threadIdx.x == 511) g_blocksum[l * 128 + blockIdx.x] = base + s;
}

__global__ void add_offsets_kernel(int n, int nb) {
    int l = blockIdx.y;
    int i = blockIdx.x * blockDim.x + threadIdx.x;
    __shared__ int sP;
    if (threadIdx.x < 32) {
        int myblk = blockIdx.x >> 1;
        int s = 0;
        for (int b = threadIdx.x; b < myblk; b += 32) s += g_blocksum[l * 128 + b];
#pragma unroll
        for (int o = 16; o; o >>= 1) s += __shfl_xor_sync(0xFFFFFFFFu, s, o);
        if (threadIdx.x == 0) sP = s;
    }
    if (blockIdx.x == 0 && threadIdx.x >= 32 && threadIdx.x < 64) {
        int lane = threadIdx.x - 32;
        int s = 0;
        for (int b = lane; b < nb; b += 32) s += g_blocksum[l * 128 + b];
#pragma unroll
        for (int o = 16; o; o >>= 1) s += __shfl_xor_sync(0xFFFFFFFFu, s, o);
        if (lane == 0) g_rowstart[l * (NMAX + 1) + n] = s;
    }
    __syncthreads();
    if (i < n) {
        g_rowstart[l * (NMAX + 1) + i] += sP;
        g_cursor[l * NMAX + i] = 0;
    }
}

__global__ void fill_kernel(const int* __restrict__ e0, const int* __restrict__ e1, int nE) {
    int i = blockIdx.x * blockDim.x + threadIdx.x;
    if (i >= 2 * nE) return;
    int l = (i < nE) ? 0 : 1;
    const int* p = l ? e1 : e0;
    int e = l ? (i - nE) : i;
    int d = p[e];
    int c = p[nE + e];
    int pos = g_rowstart[l * (NMAX + 1) + d] + atomicAdd(&g_cursor[l * NMAX + d], 1);
    g_cols[l * EMAX + pos] = c;
}

// ---- Theta conversion (once): fp32 [192,64] -> fragment-order bf16 hi/lo --
// g_Bfrag[tt][ks][tile][lane] = {b0h, b1h, b0l, b1l} for mma.m16n8k16 col B.
__global__ void convert_theta_kernel(const float* __restrict__ t1,
                                     const float* __restrict__ t2,
                                     const float* __restrict__ t3) {
    int i = blockIdx.x * blockDim.x + threadIdx.x;
    if (i >= 3 * 12 * 8 * 32) return;
    int tt = i / 3072;
    int r = i % 3072;
    int ks = r >> 8;            // k16 step (0..11)
    int j  = (r >> 5) & 7;      // n8 tile (0..7)
    int l  = r & 31;            // lane
    int g = l >> 2, q = l & 3;
    int nn = j * 8 + g;
    int k0 = ks * 16 + 2 * q;
    const float* T = (tt == 0) ? t1 : (tt == 1) ? t2 : t3;
    float x0 = T[(size_t)k0 * 64 + nn];
    float x1 = T[(size_t)(k0 + 1) * 64 + nn];
    float y0 = T[(size_t)(k0 + 8) * 64 + nn];
    float y1 = T[(size_t)(k0 + 9) * 64 + nn];
    __nv_bfloat162 b0h = __floats2bfloat162_rn(x0, x1);
    __nv_bfloat162 b1h = __floats2bfloat162_rn(y0, y1);
    __nv_bfloat162 b0l = __floats2bfloat162_rn(x0 - __low2float(b0h),
                                               x1 - __high2float(b0h));
    __nv_bfloat162 b1l = __floats2bfloat162_rn(y0 - __low2float(b1h),
                                               y1 - __high2float(b1h));
    g_Bfrag[i] = make_uint4(*(uint32_t*)&b0h, *(uint32_t*)&b1h,
                            *(uint32_t*)&b0l, *(uint32_t*)&b1l);
}

// ---- mma.sync GEMM --------------------------------------------------------
// Per CTA: rows [rowBase, rowBase+64), all 192 output cols (3 thetas).
// 512 threads / 16 warps: (w&3) -> m16 group, (w>>2) -> n16 group (2 tiles).
// smem: Ah[64][200] bf16 | Al[64][200] bf16 | Bfrag[12][8][32] uint4
#define A_STRIDE 200
#define OFF_AH 0
#define OFF_AL 25600
#define OFF_BF 51200
#define GEMM_SMEM_BYTES 100352

#define MMA(C, A0, A1, A2, A3, B0, B1)                                  \
    asm("mma.sync.aligned.m16n8k16.row.col.f32.bf16.bf16.f32 "          \
        "{%0,%1,%2,%3}, {%4,%5,%6,%7}, {%8,%9}, {%0,%1,%2,%3};"         \
        : "+f"(C.x), "+f"(C.y), "+f"(C.z), "+f"(C.w)                    \
        : "r"(A0), "r"(A1), "r"(A2), "r"(A3), "r"(B0), "r"(B1))

#define LDMX4(R0, R1, R2, R3, ADDR)                                     \
    asm volatile("ldmatrix.sync.aligned.m8n8.x4.shared.b16 "            \
                 "{%0,%1,%2,%3}, [%4];"                                 \
                 : "=r"(R0), "=r"(R1), "=r"(R2), "=r"(R3) : "r"(ADDR))

__global__ __launch_bounds__(512, 2)
void gemm_kernel(const float* __restrict__ A,
                 float* __restrict__ dst,   // n x 192 (theta0 -> cols 0:64)
                 float* __restrict__ Y,     // n x 128 (theta1|theta2)
                 int n)
{
    extern __shared__ char smem[];
    uint32_t* Ah32 = (uint32_t*)(smem + OFF_AH);
    uint32_t* Al32 = (uint32_t*)(smem + OFF_AL);
    uint4*    Bs   = (uint4*)(smem + OFF_BF);

    const int tid = threadIdx.x;
    const int w = tid >> 5;
    const int lane = tid & 31;
    const int mw = w & 3;          // m16 row-group index (BM=64)
    const int nq = w >> 2;         // n16 group (tiles nq*2, nq*2+1)
    const int q = lane & 3;
    const int rowBase = blockIdx.x * 64;

    // ---- Convert A rows to bf16 hi/lo in smem (coalesced, conflict-free) --
    for (int f = tid; f < 64 * 96; f += 512) {
        int r = f / 96, k2 = f % 96;
        int gr = rowBase + r;
        float2 v = make_float2(0.f, 0.f);
        if (gr < n) v = *(const float2*)(A + (size_t)gr * DIM + 2 * k2);
        __nv_bfloat162 hh = __floats2bfloat162_rn(v.x, v.y);
        float r0 = v.x - __low2float(hh);
        float r1 = v.y - __high2float(hh);
        __nv_bfloat162 ll = __floats2bfloat162_rn(r0, r1);
        Ah32[r * 100 + k2] = *(uint32_t*)&hh;
        Al32[r * 100 + k2] = *(uint32_t*)&ll;
    }

    // ---- per-lane ldmatrix A base addresses ----
    const uint32_t sb = smem_to_u32(smem);
    const int raA = (lane & 7) + ((lane >> 3) & 1) * 8;
    const int kaA = ((lane >> 4) & 1) * 8;
    uint32_t aAh = sb + OFF_AH + (uint32_t)((mw * 16 + raA) * A_STRIDE + kaA) * 2;
    uint32_t aAl = aAh + (OFF_AL - OFF_AH);

    // B fragment smem base for this warp's two tiles
    const uint4* Bq = Bs + (nq * 2) * 32 + lane;   // + ks*256 per kstep; +32 for tile 1

    const int row0 = rowBase + mw * 16 + (lane >> 2);
    const int row1 = row0 + 8;

#pragma unroll
    for (int tt = 0; tt < 3; ++tt) {
        __syncthreads();   // previous theta's B readers done (and A ready)
        {
            const uint4* gB = g_Bfrag + tt * 3072;
            for (int f = tid; f < 3072; f += 512) Bs[f] = gB[f];
        }
        __syncthreads();

        float4 c0 = make_float4(0.f, 0.f, 0.f, 0.f), c1 = c0;

#pragma unroll 3
        for (int ks = 0; ks < 12; ++ks) {
            const uint32_t ko = (uint32_t)ks * 32;   // 16 bf16 = 32 bytes
            uint32_t ah0, ah1, ah2, ah3, al0, al1, al2, al3;
            LDMX4(ah0, ah1, ah2, ah3, aAh + ko);
            LDMX4(al0, al1, al2, al3, aAl + ko);
            uint4 B0 = Bq[ks * 256];        // tile nq*2   {b0h,b1h,b0l,b1l}
            uint4 B1 = Bq[ks * 256 + 32];   // tile nq*2+1
            MMA(c0, ah0, ah1, ah2, ah3, B0.x, B0.y);
            MMA(c1, ah0, ah1, ah2, ah3, B1.x, B1.y);
            MMA(c0, ah0, ah1, ah2, ah3, B0.z, B0.w);
            MMA(c1, ah0, ah1, ah2, ah3, B1.z, B1.w);
            MMA(c0, al0, al1, al2, al3, B0.x, B0.y);
            MMA(c1, al0, al1, al2, al3, B1.x, B1.y);
        }

        // ---- Epilogue for this theta ----
        float* outp = (tt == 0) ? dst : Y;
        const int ostr = (tt == 0) ? DIM : 128;
        const int cb = ((tt == 2) ? 64 : 0) + nq * 16;
#define ST_TILE(C, J)                                                         \
        {                                                                     \
            int col = cb + (J) * 8 + 2 * q;                                   \
            if (row0 < n)                                                     \
                *(float2*)(outp + (size_t)row0 * ostr + col) =                \
                    make_float2(C.x, C.y);                                    \
            if (row1 < n)                                                     \
                *(float2*)(outp + (size_t)row1 * ostr + col) =                \
                    make_float2(C.z, C.w);                                    \
        }
        ST_TILE(c0, 0) ST_TILE(c1, 1)
#undef ST_TILE
    }
}

// ---- Aggregation: warp per node, atomic-free CSR gather -------------------
__global__ void agg_kernel(const float* __restrict__ Y, float* __restrict__ dst, int n)
{
    int gw = (blockIdx.x * blockDim.x + threadIdx.x) >> 5;
    int lane = threadIdx.x & 31;
    if (gw >= n) return;
#pragma unroll
    for (int l = 0; l < 2; ++l) {
        const int* rs = g_rowstart + l * (NMAX + 1);
        const int* cs = g_cols + l * EMAX;
        int s = __ldg(rs + gw);
        int e = __ldg(rs + gw + 1);
        const float* Yb = Y + l * 64 + lane * 2;
        float ax = 0.f, ay = 0.f;
        int j = s;
        for (; j + 4 <= e; j += 4) {
            int c0 = cs[j], c1 = cs[j + 1], c2 = cs[j + 2], c3 = cs[j + 3];
            float2 v0 = *(const float2*)(Yb + (size_t)c0 * 128);
            float2 v1 = *(const float2*)(Yb + (size_t)c1 * 128);
            float2 v2 = *(const float2*)(Yb + (size_t)c2 * 128);
            float2 v3 = *(const float2*)(Yb + (size_t)c3 * 128);
            ax += (v0.x + v1.x) + (v2.x + v3.x);
            ay += (v0.y + v1.y) + (v2.y + v3.y);
        }
        for (; j < e; ++j) {
            float2 v = *(const float2*)(Yb + (size_t)cs[j] * 128);
            ax += v.x; ay += v.y;
        }
        float2 o = make_float2(ax, ay);
        *(float2*)(dst + (size_t)gw * DIM + 64 + l * 64 + lane * 2) = o;
    }
}

// ---------------------------------------------------------------------------
extern "C" void kernel_launch(void* const* d_in, const int* in_sizes, int n_in,
                              void* d_out, int out_size)
{
    const float* emb = (const float*)d_in[0];
    const float* t1  = (const float*)d_in[1];
    const float* t2  = (const float*)d_in[2];
    const float* t3  = (const float*)d_in[3];
    const int*   e0  = (const int*)d_in[4];
    const int*   e1  = (const int*)d_in[5];

    int n  = in_sizes[0] / DIM;
    int nE = in_sizes[4] / 2;
    float* out = (float*)d_out;

    void *p_emb1_v, *p_Y_v;
    cudaGetSymbolAddress(&p_emb1_v, g_emb1);
    cudaGetSymbolAddress(&p_Y_v, g_Y);
    float* p_emb1 = (float*)p_emb1_v;
    float* p_Y    = (float*)p_Y_v;

    cudaFuncSetAttribute(gemm_kernel, cudaFuncAttributeMaxDynamicSharedMemorySize,
                         GEMM_SMEM_BYTES);

    int nb = (n + 511) / 512;
    int gemm_blocks = (n + 63) / 64;
    int agg_blocks = (n * 32 + 255) / 256;

    // gemm1 at launch slot #4 (the slot ncu captures) for profiling.
    zero_counts_kernel<<<(2 * NMAX + 255) / 256, 256>>>();                 // 1
    hist_kernel<<<(2 * nE + 255) / 256, 256>>>(e0, e1, nE);                // 2
    convert_theta_kernel<<<(3 * 12 * 8 * 32 + 255) / 256, 256>>>(t1, t2, t3); // 3
    gemm_kernel<<<gemm_blocks, 512, GEMM_SMEM_BYTES>>>(emb, p_emb1, p_Y, n); // 4
    dim3 gscan(nb, 2);
    scan_partial_kernel<<<gscan, 512>>>(n);                                // 5
    dim3 goff((n + 255) / 256, 2);
    add_offsets_kernel<<<goff, 256>>>(n, nb);                              // 6
    fill_kernel<<<(2 * nE + 255) / 256, 256>>>(e0, e1, nE);                // 7
    agg_kernel<<<agg_blocks, 256>>>(p_Y, p_emb1, n);                       // 8
    gemm_kernel<<<gemm_blocks, 512, GEMM_SMEM_BYTES>>>(p_emb1, out, p_Y, n); // 9
    agg_kernel<<<agg_blocks, 256>>>(p_Y, out, n);                          // 10
}

// round 10
// speedup vs baseline: 1.1310x; 1.1310x over previous
#include <cuda_runtime.h>
#include <cuda_bf16.h>
#include <cstdint>

// ---------------------------------------------------------------------------
// IterativeEmbeddingModel: 2 iterations of
//   emb <- concat(emb@T1, seg_sum(emb[col],row)@T2, seg_sum_anti(...)@T3)
// R10: exact R8 structure (BM=128, 512 thr, warp m16xn32 — best: 186.4us,
//      gemm 60.8us) with ONE change: inner-loop MMA schedule interleaves the
//      4 independent accumulators (dependency distance 1 -> 4) instead of
//      firing 3 dependent MMAs back-to-back into each accumulator.
//      R9's BM=64/occupancy experiment regressed (occ wasn't binding) — reverted.
// ---------------------------------------------------------------------------

#define NMAX 50000
#define EMAX 400000
#define DIM  192
#define PP   64

// Scratch (device globals; no allocation APIs allowed)
__device__ int      g_count[2 * NMAX];
__device__ int      g_cursor[2 * NMAX];
__device__ int      g_rowstart[2 * (NMAX + 1)];
__device__ int      g_blocksum[2 * 128];
__device__ int      g_cols[2 * EMAX];
__device__ float    g_emb1[(size_t)NMAX * DIM];   // iteration-1 output
__device__ float    g_Y[(size_t)NMAX * 128];      // [Y2 | Y3] per row
__device__ uint32_t g_Bh32[3 * 64 * 96];          // thetas bf16-hi, [t][n][k] pairs
__device__ uint32_t g_Bl32[3 * 64 * 96];          // thetas bf16-lo

__device__ __forceinline__ uint32_t smem_to_u32(const void* p) {
    uint32_t a;
    asm("{ .reg .u64 t; cvta.to.shared.u64 t, %1; cvt.u32.u64 %0, t; }"
        : "=r"(a) : "l"(p));
    return a;
}

// ---- CSR build ------------------------------------------------------------
__global__ void zero_counts_kernel() {
    int i = blockIdx.x * blockDim.x + threadIdx.x;
    if (i < 2 * NMAX) g_count[i] = 0;
}

__global__ void hist_kernel(const int* __restrict__ e0, const int* __restrict__ e1, int nE) {
    int i = blockIdx.x * blockDim.x + threadIdx.x;
    if (i >= 2 * nE) return;
    int l = (i < nE) ? 0 : 1;
    const int* p = l ? e1 : e0;
    int e = l ? (i - nE) : i;
    int d = p[e];
    atomicAdd(&g_count[l * NMAX + d], 1);
}

__global__ void scan_partial_kernel(int n) {
    __shared__ int warp_sums[16];
    int l = blockIdx.y;
    int i = blockIdx.x * 512 + threadIdx.x;
    int lane = threadIdx.x & 31;
    int w = threadIdx.x >> 5;
    int v = (i < n) ? g_count[l * NMAX + i] : 0;
    int s = v;
#pragma unroll
    for (int o = 1; o < 32; o <<= 1) {
        int t = __shfl_up_sync(0xFFFFFFFFu, s, o);
        if (lane >= o) s += t;
    }
    if (lane == 31) warp_sums[w] = s;
    __syncthreads();
    if (w == 0) {
        int ws = (lane < 16) ? warp_sums[lane] : 0;
#pragma unroll
        for (int o = 1; o < 16; o <<= 1) {
            int t = __shfl_up_sync(0xFFFFFFFFu, ws, o);
            if (lane >= o) ws += t;
        }
        if (lane < 16) warp_sums[lane] = ws;
    }
    __syncthreads();
    int base = (w > 0) ? warp_sums[w - 1] : 0;
    if (i < n) g_rowstart[l * (NMAX + 1) + i] = base + s - v;
    if (threadIdx.x == 511) g_blocksum[l * 128 + blockIdx.x] = base + s;
}

__global__ void add_offsets_kernel(int n, int nb) {
    int l = blockIdx.y;
    int i = blockIdx.x * blockDim.x + threadIdx.x;
    __shared__ int sP;
    if (threadIdx.x < 32) {
        int myblk = blockIdx.x >> 1;
        int s = 0;
        for (int b = threadIdx.x; b < myblk; b += 32) s += g_blocksum[l * 128 + b];
#pragma unroll
        for (int o = 16; o; o >>= 1) s += __shfl_xor_sync(0xFFFFFFFFu, s, o);
        if (threadIdx.x == 0) sP = s;
    }
    if (blockIdx.x == 0 && threadIdx.x >= 32 && threadIdx.x < 64) {
        int lane = threadIdx.x - 32;
        int s = 0;
        for (int b = lane; b < nb; b += 32) s += g_blocksum[l * 128 + b];
#pragma unroll
        for (int o = 16; o; o >>= 1) s += __shfl_xor_sync(0xFFFFFFFFu, s, o);
        if (lane == 0) g_rowstart[l * (NMAX + 1) + n] = s;
    }
    __syncthreads();
    if (i < n) {
        g_rowstart[l * (NMAX + 1) + i] += sP;
        g_cursor[l * NMAX + i] = 0;
    }
}

__global__ void fill_kernel(const int* __restrict__ e0, const int* __restrict__ e1, int nE) {
    int i = blockIdx.x * blockDim.x + threadIdx.x;
    if (i >= 2 * nE) return;
    int l = (i < nE) ? 0 : 1;
    const int* p = l ? e1 : e0;
    int e = l ? (i - nE) : i;
    int d = p[e];
    int c = p[nE + e];
    int pos = g_rowstart[l * (NMAX + 1) + d] + atomicAdd(&g_cursor[l * NMAX + d], 1);
    g_cols[l * EMAX + pos] = c;
}

// ---- Theta conversion (once): fp32 [192,64] -> bf16 hi/lo [t][n][192] -----
__global__ void convert_theta_kernel(const float* __restrict__ t1,
                                     const float* __restrict__ t2,
                                     const float* __restrict__ t3) {
    int i = blockIdx.x * blockDim.x + threadIdx.x;   // over 3*64*96 u32 pairs
    if (i >= 3 * 64 * 96) return;
    int tt = i / 6144;
    int rem = i % 6144;
    int nn = rem / 96;
    int k2 = rem % 96;
    const float* T = (tt == 0) ? t1 : (tt == 1) ? t2 : t3;
    float x0 = T[(size_t)(2 * k2) * 64 + nn];
    float x1 = T[(size_t)(2 * k2 + 1) * 64 + nn];
    __nv_bfloat162 hh = __floats2bfloat162_rn(x0, x1);
    float r0 = x0 - __low2float(hh);
    float r1 = x1 - __high2float(hh);
    __nv_bfloat162 ll = __floats2bfloat162_rn(r0, r1);
    g_Bh32[i] = *(uint32_t*)&hh;
    g_Bl32[i] = *(uint32_t*)&ll;
}

// ---- mma.sync GEMM --------------------------------------------------------
// Per CTA: rows [rowBase, rowBase+128), all 192 output cols (3 thetas).
// 512 threads / 16 warps: warp (w&7) -> m16 row group, (w>>3) -> n half (32).
// smem (bf16 elems, row stride 200 = 4 banks -> conflict-free ldmatrix):
//   Ah[128][200] | Al[128][200] | Bh[64][200] | Bl[64][200]
#define A_STRIDE 200
#define OFF_AH 0
#define OFF_AL 51200
#define OFF_BH 102400
#define OFF_BL 128000
#define GEMM_SMEM_BYTES 153600

#define MMA(C, A0, A1, A2, A3, B0, B1)                                  \
    asm("mma.sync.aligned.m16n8k16.row.col.f32.bf16.bf16.f32 "          \
        "{%0,%1,%2,%3}, {%4,%5,%6,%7}, {%8,%9}, {%0,%1,%2,%3};"         \
        : "+f"(C.x), "+f"(C.y), "+f"(C.z), "+f"(C.w)                    \
        : "r"(A0), "r"(A1), "r"(A2), "r"(A3), "r"(B0), "r"(B1))

#define LDMX4(R0, R1, R2, R3, ADDR)                                     \
    asm volatile("ldmatrix.sync.aligned.m8n8.x4.shared.b16 "            \
                 "{%0,%1,%2,%3}, [%4];"                                 \
                 : "=r"(R0), "=r"(R1), "=r"(R2), "=r"(R3) : "r"(ADDR))

__global__ __launch_bounds__(512, 1)
void gemm_kernel(const float* __restrict__ A,
                 float* __restrict__ dst,   // n x 192 (theta0 -> cols 0:64)
                 float* __restrict__ Y,     // n x 128 (theta1|theta2)
                 int n)
{
    extern __shared__ char smem[];
    uint32_t* Ah32 = (uint32_t*)(smem + OFF_AH);
    uint32_t* Al32 = (uint32_t*)(smem + OFF_AL);
    uint32_t* Bh32 = (uint32_t*)(smem + OFF_BH);
    uint32_t* Bl32 = (uint32_t*)(smem + OFF_BL);

    const int tid = threadIdx.x;
    const int w = tid >> 5;
    const int lane = tid & 31;
    const int mw = w & 7;          // m16 row-group index
    const int nh = w >> 3;         // n half (0: cols 0-31, 1: cols 32-63)
    const int q = lane & 3;
    const int rowBase = blockIdx.x * 128;

    // ---- Convert A rows to bf16 hi/lo in smem (coalesced, conflict-free) --
    for (int f = tid; f < 128 * 96; f += 512) {
        int r = f / 96, k2 = f % 96;
        int gr = rowBase + r;
        float2 v = make_float2(0.f, 0.f);
        if (gr < n) v = *(const float2*)(A + (size_t)gr * DIM + 2 * k2);
        __nv_bfloat162 hh = __floats2bfloat162_rn(v.x, v.y);
        float r0 = v.x - __low2float(hh);
        float r1 = v.y - __high2float(hh);
        __nv_bfloat162 ll = __floats2bfloat162_rn(r0, r1);
        Ah32[r * 100 + k2] = *(uint32_t*)&hh;
        Al32[r * 100 + k2] = *(uint32_t*)&ll;
    }

    // ---- per-lane ldmatrix base addresses (byte addresses in shared) ----
    const uint32_t sb = smem_to_u32(smem);
    // A x4: lanes 0-7 m0(r+0,k+0), 8-15 m1(r+8,k+0), 16-23 m2(r+0,k+8), 24-31 m3(r+8,k+8)
    const int raA = (lane & 7) + ((lane >> 3) & 1) * 8;
    const int kaA = ((lane >> 4) & 1) * 8;
    uint32_t aAh = sb + OFF_AH + (uint32_t)((mw * 16 + raA) * A_STRIDE + kaA) * 2;
    uint32_t aAl = aAh + (OFF_AL - OFF_AH);
    // B x4 over a tile pair: m0(t0,k+0), m1(t0,k+8), m2(t1,k+0), m3(t1,k+8)
    const int rbB = (lane & 7) + ((lane >> 4) & 1) * 8;
    const int kbB = ((lane >> 3) & 1) * 8;
    uint32_t aB0h = sb + OFF_BH + (uint32_t)((nh * 32 + rbB) * A_STRIDE + kbB) * 2;
    uint32_t aB1h = aB0h + 16 * A_STRIDE * 2;
    uint32_t aB0l = aB0h + (OFF_BL - OFF_BH);
    uint32_t aB1l = aB1h + (OFF_BL - OFF_BH);

    const int row0 = rowBase + mw * 16 + (lane >> 2);
    const int row1 = row0 + 8;

#pragma unroll
    for (int tt = 0; tt < 3; ++tt) {
        __syncthreads();   // previous theta's B readers done (and A ready)
        {
            const uint32_t* gh = g_Bh32 + tt * 6144;
            const uint32_t* gl = g_Bl32 + tt * 6144;
            for (int f = tid; f < 64 * 96; f += 512) {
                int nn = f / 96, k2 = f % 96;
                Bh32[nn * 100 + k2] = gh[f];
                Bl32[nn * 100 + k2] = gl[f];
            }
        }
        __syncthreads();

        float4 c0 = make_float4(0.f, 0.f, 0.f, 0.f), c1 = c0, c2 = c0, c3 = c0;

#pragma unroll 2
        for (int ks = 0; ks < 12; ++ks) {
            const uint32_t ko = (uint32_t)ks * 32;   // 16 bf16 = 32 bytes

            // Load ALL fragments first (A hi/lo, B hi/lo for all 4 tiles).
            uint32_t ah0, ah1, ah2, ah3, al0, al1, al2, al3;
            LDMX4(ah0, ah1, ah2, ah3, aAh + ko);
            LDMX4(al0, al1, al2, al3, aAl + ko);
            uint32_t b0h0, b0h1, b1h0, b1h1;
            LDMX4(b0h0, b0h1, b1h0, b1h1, aB0h + ko);
            uint32_t b2h0, b2h1, b3h0, b3h1;
            LDMX4(b2h0, b2h1, b3h0, b3h1, aB1h + ko);
            uint32_t b0l0, b0l1, b1l0, b1l1;
            LDMX4(b0l0, b0l1, b1l0, b1l1, aB0l + ko);
            uint32_t b2l0, b2l1, b3l0, b3l1;
            LDMX4(b2l0, b2l1, b3l0, b3l1, aB1l + ko);

            // Interleaved schedule: dependency distance 4 (was 1).
            MMA(c0, ah0, ah1, ah2, ah3, b0h0, b0h1);
            MMA(c1, ah0, ah1, ah2, ah3, b1h0, b1h1);
            MMA(c2, ah0, ah1, ah2, ah3, b2h0, b2h1);
            MMA(c3, ah0, ah1, ah2, ah3, b3h0, b3h1);
            MMA(c0, ah0, ah1, ah2, ah3, b0l0, b0l1);
            MMA(c1, ah0, ah1, ah2, ah3, b1l0, b1l1);
            MMA(c2, ah0, ah1, ah2, ah3, b2l0, b2l1);
            MMA(c3, ah0, ah1, ah2, ah3, b3l0, b3l1);
            MMA(c0, al0, al1, al2, al3, b0h0, b0h1);
            MMA(c1, al0, al1, al2, al3, b1h0, b1h1);
            MMA(c2, al0, al1, al2, al3, b2h0, b2h1);
            MMA(c3, al0, al1, al2, al3, b3h0, b3h1);
        }

        // ---- Epilogue for this theta ----
        float* outp = (tt == 0) ? dst : Y;
        const int ostr = (tt == 0) ? DIM : 128;
        const int cb = ((tt == 2) ? 64 : 0) + nh * 32;
#define ST_TILE(C, J)                                                         \
        {                                                                     \
            int col = cb + (J) * 8 + 2 * q;                                   \
            if (row0 < n)                                                     \
                *(float2*)(outp + (size_t)row0 * ostr + col) =                \
                    make_float2(C.x, C.y);                                    \
            if (row1 < n)                                                     \
                *(float2*)(outp + (size_t)row1 * ostr + col) =                \
                    make_float2(C.z, C.w);                                    \
        }
        ST_TILE(c0, 0) ST_TILE(c1, 1) ST_TILE(c2, 2) ST_TILE(c3, 3)
#undef ST_TILE
    }
}

// ---- Aggregation: warp per node, atomic-free CSR gather -------------------
__global__ void agg_kernel(const float* __restrict__ Y, float* __restrict__ dst, int n)
{
    int gw = (blockIdx.x * blockDim.x + threadIdx.x) >> 5;
    int lane = threadIdx.x & 31;
    if (gw >= n) return;
#pragma unroll
    for (int l = 0; l < 2; ++l) {
        const int* rs = g_rowstart + l * (NMAX + 1);
        const int* cs = g_cols + l * EMAX;
        int s = __ldg(rs + gw);
        int e = __ldg(rs + gw + 1);
        const float* Yb = Y + l * 64 + lane * 2;
        float ax = 0.f, ay = 0.f;
        int j = s;
        for (; j + 4 <= e; j += 4) {
            int c0 = cs[j], c1 = cs[j + 1], c2 = cs[j + 2], c3 = cs[j + 3];
            float2 v0 = *(const float2*)(Yb + (size_t)c0 * 128);
            float2 v1 = *(const float2*)(Yb + (size_t)c1 * 128);
            float2 v2 = *(const float2*)(Yb + (size_t)c2 * 128);
            float2 v3 = *(const float2*)(Yb + (size_t)c3 * 128);
            ax += (v0.x + v1.x) + (v2.x + v3.x);
            ay += (v0.y + v1.y) + (v2.y + v3.y);
        }
        for (; j < e; ++j) {
            float2 v = *(const float2*)(Yb + (size_t)cs[j] * 128);
            ax += v.x; ay += v.y;
        }
        float2 o = make_float2(ax, ay);
        *(float2*)(dst + (size_t)gw * DIM + 64 + l * 64 + lane * 2) = o;
    }
}

// ---------------------------------------------------------------------------
extern "C" void kernel_launch(void* const* d_in, const int* in_sizes, int n_in,
                              void* d_out, int out_size)
{
    const float* emb = (const float*)d_in[0];
    const float* t1  = (const float*)d_in[1];
    const float* t2  = (const float*)d_in[2];
    const float* t3  = (const float*)d_in[3];
    const int*   e0  = (const int*)d_in[4];
    const int*   e1  = (const int*)d_in[5];

    int n  = in_sizes[0] / DIM;
    int nE = in_sizes[4] / 2;
    float* out = (float*)d_out;

    void *p_emb1_v, *p_Y_v;
    cudaGetSymbolAddress(&p_emb1_v, g_emb1);
    cudaGetSymbolAddress(&p_Y_v, g_Y);
    float* p_emb1 = (float*)p_emb1_v;
    float* p_Y    = (float*)p_Y_v;

    cudaFuncSetAttribute(gemm_kernel, cudaFuncAttributeMaxDynamicSharedMemorySize,
                         GEMM_SMEM_BYTES);

    int nb = (n + 511) / 512;
    int gemm_blocks = (n + 127) / 128;
    int agg_blocks = (n * 32 + 255) / 256;

    // gemm1 at launch slot #4 (the slot ncu captures) for profiling.
    zero_counts_kernel<<<(2 * NMAX + 255) / 256, 256>>>();                 // 1
    hist_kernel<<<(2 * nE + 255) / 256, 256>>>(e0, e1, nE);                // 2
    convert_theta_kernel<<<(3 * 64 * 96 + 255) / 256, 256>>>(t1, t2, t3);  // 3
    gemm_kernel<<<gemm_blocks, 512, GEMM_SMEM_BYTES>>>(emb, p_emb1, p_Y, n); // 4
    dim3 gscan(nb, 2);
    scan_partial_kernel<<<gscan, 512>>>(n);                                // 5
    dim3 goff((n + 255) / 256, 2);
    add_offsets_kernel<<<goff, 256>>>(n, nb);                              // 6
    fill_kernel<<<(2 * nE + 255) / 256, 256>>>(e0, e1, nE);                // 7
    agg_kernel<<<agg_blocks, 256>>>(p_Y, p_emb1, n);                       // 8
    gemm_kernel<<<gemm_blocks, 512, GEMM_SMEM_BYTES>>>(p_emb1, out, p_Y, n); // 9
    agg_kernel<<<agg_blocks, 256>>>(p_Y, out, n);                          // 10
}